// round 6
// baseline (speedup 1.0000x reference)
#include <cuda_runtime.h>
#include <cuda_bf16.h>
#include <cstdint>

#define NNODES 20000
#define NEDGES 160000
#define F_IN   512
#define F_HID  512
#define F_OUT  256

// ---------------- scratch (device globals; no allocation APIs allowed) -----
__device__ int   g_is64;
__device__ int   g_deg[NNODES];
__device__ int   g_rowptr[NNODES + 1];
__device__ int   g_cursor[NNODES];
__device__ int   g_srcs[NEDGES];
__device__ __align__(16) float g_dinv[NNODES];
__device__ __align__(16) float g_h1[(size_t)NNODES * F_HID];
__device__ __align__(16) float g_a1[(size_t)NNODES * F_HID];
__device__ __align__(16) float g_h2[(size_t)NNODES * F_OUT];

// ---------------- edge index access (dtype-agnostic) ------------------------
__device__ __forceinline__ int2 edge_at(const void* ei, int e) {
    if (g_is64) {
        const long long* p = (const long long*)ei;
        return make_int2((int)p[e], (int)p[NEDGES + e]);
    } else {
        const int* p = (const int*)ei;
        return make_int2(p[e], p[NEDGES + e]);
    }
}

// int64 little-endian with values < 2^31 -> every odd int32 word is 0.
__global__ void detect_dtype_kernel(const int* ei) {
    if (threadIdx.x == 0 && blockIdx.x == 0) {
        int is64 = 1;
        for (int i = 1; i < 64; i += 2)
            if (ei[i] != 0) { is64 = 0; break; }
        g_is64 = is64;
    }
}

__global__ void zero_deg_kernel() {
    int i = blockIdx.x * blockDim.x + threadIdx.x;
    if (i < NNODES) g_deg[i] = 0;
}

__global__ void deg_count_kernel(const void* ei) {
    int e = blockIdx.x * blockDim.x + threadIdx.x;
    if (e < NEDGES) {
        int2 sd = edge_at(ei, e);
        atomicAdd(&g_deg[sd.y], 1);
    }
}

// single-block exclusive scan of g_deg -> g_rowptr / g_cursor; 1024 threads
__global__ void scan_kernel() {
    __shared__ int part[1024];
    const int T = 1024, CH = (NNODES + 1023) / 1024;
    const int t = threadIdx.x;
    const int base = t * CH;
    int s = 0;
    for (int i = 0; i < CH; i++) {
        int idx = base + i;
        if (idx < NNODES) s += g_deg[idx];
    }
    part[t] = s;
    __syncthreads();
    for (int off = 1; off < T; off <<= 1) {
        int v = (t >= off) ? part[t - off] : 0;
        __syncthreads();
        part[t] += v;
        __syncthreads();
    }
    int run = (t > 0) ? part[t - 1] : 0;
    for (int i = 0; i < CH; i++) {
        int idx = base + i;
        if (idx < NNODES) {
            g_rowptr[idx] = run;
            g_cursor[idx] = run;
            run += g_deg[idx];
        }
    }
    if (t == T - 1) g_rowptr[NNODES] = part[T - 1];
}

__global__ void dinv_kernel() {
    int i = blockIdx.x * blockDim.x + threadIdx.x;
    if (i < NNODES) g_dinv[i] = rsqrtf(1.0f + (float)g_deg[i]);
}

__global__ void fill_kernel(const void* ei) {
    int e = blockIdx.x * blockDim.x + threadIdx.x;
    if (e < NEDGES) {
        int2 sd = edge_at(ei, e);
        int pos = atomicAdd(&g_cursor[sd.y], 1);
        g_srcs[pos] = sd.x;
    }
}

// ---------------- SIMT fp32 GEMM, 128x128x8, 8x8/thread, double-buffered ---
// (UNCHANGED from R5 for clean profile attribution)
__global__ __launch_bounds__(256, 2)
void sgemm128_kernel(const float* __restrict__ A, const float* __restrict__ B,
                     float* __restrict__ C, int M, int N, int K) {
    constexpr int BM = 128, BN = 128, BK = 8;
    __shared__ float As[2][BK][BM];
    __shared__ float Bs[2][BK][BN];

    const int tid = threadIdx.x;
    const int block_row = blockIdx.y * BM;
    const int block_col = blockIdx.x * BN;

    const int a_row  = tid >> 1;
    const int a_col4 = (tid & 1) * 4;
    const int b_row  = tid >> 5;
    const int b_col4 = (tid & 31) * 4;

    const int ty = tid >> 4;
    const int tx = tid & 15;

    const int a_g_row = block_row + a_row;
    const bool a_ok = a_g_row < M;
    const float* a_ptr = A + (size_t)(a_ok ? a_g_row : 0) * K + a_col4;
    const float* b_ptr = B + (size_t)b_row * N + block_col + b_col4;

    float acc[8][8];
    #pragma unroll
    for (int i = 0; i < 8; i++)
        #pragma unroll
        for (int j = 0; j < 8; j++) acc[i][j] = 0.f;

    {
        float4 av = a_ok ? *reinterpret_cast<const float4*>(a_ptr)
                         : make_float4(0.f, 0.f, 0.f, 0.f);
        float4 bv = *reinterpret_cast<const float4*>(b_ptr);
        As[0][a_col4 + 0][a_row] = av.x;
        As[0][a_col4 + 1][a_row] = av.y;
        As[0][a_col4 + 2][a_row] = av.z;
        As[0][a_col4 + 3][a_row] = av.w;
        *reinterpret_cast<float4*>(&Bs[0][b_row][b_col4]) = bv;
    }
    __syncthreads();

    const int nsteps = K / BK;
    for (int k0 = 0; k0 < nsteps; k0++) {
        const int buf = k0 & 1;
        float4 av, bv;
        const bool has_next = (k0 + 1) < nsteps;
        if (has_next) {
            const float* ap = a_ptr + (size_t)(k0 + 1) * BK;
            av = a_ok ? *reinterpret_cast<const float4*>(ap)
                      : make_float4(0.f, 0.f, 0.f, 0.f);
            bv = *reinterpret_cast<const float4*>(b_ptr + (size_t)(k0 + 1) * BK * N);
        }

        #pragma unroll
        for (int k = 0; k < BK; k++) {
            float4 ra0 = *reinterpret_cast<const float4*>(&As[buf][k][ty * 4]);
            float4 ra1 = *reinterpret_cast<const float4*>(&As[buf][k][ty * 4 + 64]);
            float4 rb0 = *reinterpret_cast<const float4*>(&Bs[buf][k][tx * 4]);
            float4 rb1 = *reinterpret_cast<const float4*>(&Bs[buf][k][tx * 4 + 64]);
            const float ra[8] = {ra0.x, ra0.y, ra0.z, ra0.w, ra1.x, ra1.y, ra1.z, ra1.w};
            const float rb[8] = {rb0.x, rb0.y, rb0.z, rb0.w, rb1.x, rb1.y, rb1.z, rb1.w};
            #pragma unroll
            for (int i = 0; i < 8; i++)
                #pragma unroll
                for (int j = 0; j < 8; j++) acc[i][j] += ra[i] * rb[j];
        }

        if (has_next) {
            const int nb = buf ^ 1;
            As[nb][a_col4 + 0][a_row] = av.x;
            As[nb][a_col4 + 1][a_row] = av.y;
            As[nb][a_col4 + 2][a_row] = av.z;
            As[nb][a_col4 + 3][a_row] = av.w;
            *reinterpret_cast<float4*>(&Bs[nb][b_row][b_col4]) = bv;
            __syncthreads();
        }
    }

    #pragma unroll
    for (int i = 0; i < 8; i++) {
        const int lr = (i < 4) ? (ty * 4 + i) : (64 + ty * 4 + i - 4);
        const int gr = block_row + lr;
        if (gr < M) {
            float4 v0 = make_float4(acc[i][0], acc[i][1], acc[i][2], acc[i][3]);
            float4 v1 = make_float4(acc[i][4], acc[i][5], acc[i][6], acc[i][7]);
            *reinterpret_cast<float4*>(C + (size_t)gr * N + block_col + tx * 4) = v0;
            *reinterpret_cast<float4*>(C + (size_t)gr * N + block_col + 64 + tx * 4) = v1;
        }
    }
}

// ---------------- pull aggregation: WARP per node, 4-way edge ILP ----------
// out[v] = relu( sum_{src} h[src]*dinv[src]*dinv[v] + h[v]*dinv[v]^2 + b )
template <int F>
__global__ void aggregate_warp_kernel(const float* __restrict__ h,
                                      const float* __restrict__ bias,
                                      float* __restrict__ out) {
    constexpr int NV = F / 128;              // float4 chunks per lane (4 or 2)
    const int w    = threadIdx.x >> 5;       // warp in block (0..7)
    const int lane = threadIdx.x & 31;
    const int v = blockIdx.x * 8 + w;
    if (v >= NNODES) return;

    const float dv = g_dinv[v];
    const float sw = dv * dv;

    float4 acc[NV];
    {
        const float4* hv = reinterpret_cast<const float4*>(h + (size_t)v * F);
        #pragma unroll
        for (int i = 0; i < NV; i++) {
            float4 t = hv[lane + 32 * i];
            acc[i] = make_float4(t.x * sw, t.y * sw, t.z * sw, t.w * sw);
        }
    }

    const int beg = g_rowptr[v];
    const int end = g_rowptr[v + 1];
    int j = beg;
    // 4 edges per iteration: independent index/weight/row loads -> high MLP
    for (; j + 4 <= end; j += 4) {
        const int s0 = g_srcs[j + 0], s1 = g_srcs[j + 1];
        const int s2 = g_srcs[j + 2], s3 = g_srcs[j + 3];
        const float w0 = g_dinv[s0] * dv, w1 = g_dinv[s1] * dv;
        const float w2 = g_dinv[s2] * dv, w3 = g_dinv[s3] * dv;
        const float4* p0 = reinterpret_cast<const float4*>(h + (size_t)s0 * F);
        const float4* p1 = reinterpret_cast<const float4*>(h + (size_t)s1 * F);
        const float4* p2 = reinterpret_cast<const float4*>(h + (size_t)s2 * F);
        const float4* p3 = reinterpret_cast<const float4*>(h + (size_t)s3 * F);
        #pragma unroll
        for (int i = 0; i < NV; i++) {
            const int c = lane + 32 * i;
            float4 t0 = p0[c], t1 = p1[c], t2 = p2[c], t3 = p3[c];
            acc[i].x += t0.x * w0 + t1.x * w1 + t2.x * w2 + t3.x * w3;
            acc[i].y += t0.y * w0 + t1.y * w1 + t2.y * w2 + t3.y * w3;
            acc[i].z += t0.z * w0 + t1.z * w1 + t2.z * w2 + t3.z * w3;
            acc[i].w += t0.w * w0 + t1.w * w1 + t2.w * w2 + t3.w * w3;
        }
    }
    for (; j < end; j++) {
        const int s = g_srcs[j];
        const float ww = g_dinv[s] * dv;
        const float4* p = reinterpret_cast<const float4*>(h + (size_t)s * F);
        #pragma unroll
        for (int i = 0; i < NV; i++) {
            float4 t = p[lane + 32 * i];
            acc[i].x += t.x * ww; acc[i].y += t.y * ww;
            acc[i].z += t.z * ww; acc[i].w += t.w * ww;
        }
    }

    const float4* bptr = reinterpret_cast<const float4*>(bias);
    float4* optr = reinterpret_cast<float4*>(out + (size_t)v * F);
    #pragma unroll
    for (int i = 0; i < NV; i++) {
        float4 b = bptr[lane + 32 * i];
        float4 o;
        o.x = fmaxf(acc[i].x + b.x, 0.f);
        o.y = fmaxf(acc[i].y + b.y, 0.f);
        o.z = fmaxf(acc[i].z + b.z, 0.f);
        o.w = fmaxf(acc[i].w + b.w, 0.f);
        optr[lane + 32 * i] = o;
    }
}

// ---------------- launch ----------------------------------------------------
// Launch order deliberately places sgemm1 at my-launch-index 3 so the fixed
// ncu "-s 5 -c 1" capture (which previously landed on index-3 scan_kernel)
// profiles the GEMM. sgemm1 needs only x/W1 — no graph preprocessing.
extern "C" void kernel_launch(void* const* d_in, const int* in_sizes, int n_in,
                              void* d_out, int out_size) {
    const float* x  = (const float*)d_in[0];
    const void*  ei = d_in[1];
    const float* W1 = (const float*)d_in[2];
    const float* b1 = (const float*)d_in[3];
    const float* W2 = (const float*)d_in[4];
    const float* b2 = (const float*)d_in[5];
    float* out = (float*)d_out;

    detect_dtype_kernel<<<1, 32>>>((const int*)ei);                 // 0
    zero_deg_kernel<<<(NNODES + 255) / 256, 256>>>();               // 1
    deg_count_kernel<<<(NEDGES + 255) / 256, 256>>>(ei);            // 2

    {                                                               // 3 (capture)
        dim3 grid(F_HID / 128, (NNODES + 127) / 128);
        sgemm128_kernel<<<grid, 256>>>(x, W1, g_h1, NNODES, F_HID, F_IN);
    }

    scan_kernel<<<1, 1024>>>();                                     // 4
    dinv_kernel<<<(NNODES + 255) / 256, 256>>>();                   // 5
    fill_kernel<<<(NEDGES + 255) / 256, 256>>>(ei);                 // 6

    aggregate_warp_kernel<F_HID><<<(NNODES + 7) / 8, 256>>>(g_h1, b1, g_a1);  // 7

    {                                                               // 8
        dim3 grid(F_OUT / 128, (NNODES + 127) / 128);
        sgemm128_kernel<<<grid, 256>>>(g_a1, W2, g_h2, NNODES, F_OUT, F_HID);
    }
    aggregate_warp_kernel<F_OUT><<<(NNODES + 7) / 8, 256>>>(g_h2, b2, out);   // 9
}

// round 7
// speedup vs baseline: 1.0080x; 1.0080x over previous
#include <cuda_runtime.h>
#include <cuda_bf16.h>
#include <cstdint>

#define NNODES 20000
#define NEDGES 160000
#define F_IN   512
#define F_HID  512
#define F_OUT  256

// ---------------- scratch (device globals; no allocation APIs allowed) -----
__device__ int   g_is64;
__device__ int   g_deg[NNODES];
__device__ int   g_rowptr[NNODES + 1];
__device__ int   g_cursor[NNODES];
__device__ int   g_srcs[NEDGES];
__device__ __align__(16) float g_dinv[NNODES];
__device__ __align__(16) float g_h1[(size_t)NNODES * F_HID];   // (x@W1)*dinv[row]
__device__ __align__(16) float g_a1[(size_t)NNODES * F_HID];
__device__ __align__(16) float g_h2[(size_t)NNODES * F_OUT];   // (a1@W2)*dinv[row]

// ---------------- fused preprocessing: ONE block, 1024 threads --------------
// detect dtype -> zero deg -> count -> scan (rowptr/cursor/dinv) -> fill CSR
__global__ void preprocess_kernel(const void* ei) {
    const int t = threadIdx.x;                 // 0..1023
    __shared__ int s_is64;
    __shared__ int part[1024];

    if (t == 0) {
        const int* p = (const int*)ei;
        int is64 = 1;
        for (int i = 1; i < 64; i += 2)
            if (p[i] != 0) { is64 = 0; break; }
        s_is64 = is64;
        g_is64 = is64;
    }
    __syncthreads();
    const int is64 = s_is64;

    for (int i = t; i < NNODES; i += 1024) g_deg[i] = 0;
    __syncthreads();

    if (is64) {
        const long long* p = (const long long*)ei;
        for (int e = t; e < NEDGES; e += 1024)
            atomicAdd(&g_deg[(int)p[NEDGES + e]], 1);
    } else {
        const int* p = (const int*)ei;
        for (int e = t; e < NEDGES; e += 1024)
            atomicAdd(&g_deg[p[NEDGES + e]], 1);
    }
    __syncthreads();

    // chunked exclusive scan over 20000 degrees
    const int CH = (NNODES + 1023) / 1024;     // 20
    const int base = t * CH;
    int s = 0;
    for (int i = 0; i < CH; i++) {
        int idx = base + i;
        if (idx < NNODES) s += g_deg[idx];
    }
    part[t] = s;
    __syncthreads();
    for (int off = 1; off < 1024; off <<= 1) {
        int v = (t >= off) ? part[t - off] : 0;
        __syncthreads();
        part[t] += v;
        __syncthreads();
    }
    int run = (t > 0) ? part[t - 1] : 0;
    for (int i = 0; i < CH; i++) {
        int idx = base + i;
        if (idx < NNODES) {
            g_rowptr[idx] = run;
            g_cursor[idx] = run;
            g_dinv[idx] = rsqrtf(1.0f + (float)g_deg[idx]);
            run += g_deg[idx];
        }
    }
    if (t == 1023) g_rowptr[NNODES] = part[1023];
    __syncthreads();

    if (is64) {
        const long long* p = (const long long*)ei;
        for (int e = t; e < NEDGES; e += 1024) {
            int src = (int)p[e];
            int dst = (int)p[NEDGES + e];
            int pos = atomicAdd(&g_cursor[dst], 1);
            g_srcs[pos] = src;
        }
    } else {
        const int* p = (const int*)ei;
        for (int e = t; e < NEDGES; e += 1024) {
            int src = p[e];
            int dst = p[NEDGES + e];
            int pos = atomicAdd(&g_cursor[dst], 1);
            g_srcs[pos] = src;
        }
    }
}

// ---------------- L2 warm for the gather's index/weight arrays --------------
__global__ void warm_kernel() {
    const int i = blockIdx.x * blockDim.x + threadIdx.x;
    int acc = 0;
    for (int k = i; k < NEDGES; k += gridDim.x * blockDim.x) acc += g_srcs[k];
    float f = 0.f;
    for (int k = i; k < NNODES; k += gridDim.x * blockDim.x) f += g_dinv[k];
    asm volatile("" :: "r"(acc), "f"(f));   // keep loads, no stores
}

// ---------------- SIMT fp32 GEMM, 128x128x8, 8x8/thread, double-buffered ---
// C[r] = (A@B)[r] * dinv[r]  (row pre-scaling fused into epilogue)
__global__ __launch_bounds__(256, 2)
void sgemm128_scaled_kernel(const float* __restrict__ A, const float* __restrict__ B,
                            float* __restrict__ C, int M, int N, int K) {
    constexpr int BM = 128, BN = 128, BK = 8;
    __shared__ float As[2][BK][BM];
    __shared__ float Bs[2][BK][BN];

    const int tid = threadIdx.x;
    const int block_row = blockIdx.y * BM;
    const int block_col = blockIdx.x * BN;

    const int a_row  = tid >> 1;
    const int a_col4 = (tid & 1) * 4;
    const int b_row  = tid >> 5;
    const int b_col4 = (tid & 31) * 4;

    const int ty = tid >> 4;
    const int tx = tid & 15;

    const int a_g_row = block_row + a_row;
    const bool a_ok = a_g_row < M;
    const float* a_ptr = A + (size_t)(a_ok ? a_g_row : 0) * K + a_col4;
    const float* b_ptr = B + (size_t)b_row * N + block_col + b_col4;

    float acc[8][8];
    #pragma unroll
    for (int i = 0; i < 8; i++)
        #pragma unroll
        for (int j = 0; j < 8; j++) acc[i][j] = 0.f;

    {
        float4 av = a_ok ? *reinterpret_cast<const float4*>(a_ptr)
                         : make_float4(0.f, 0.f, 0.f, 0.f);
        float4 bv = *reinterpret_cast<const float4*>(b_ptr);
        As[0][a_col4 + 0][a_row] = av.x;
        As[0][a_col4 + 1][a_row] = av.y;
        As[0][a_col4 + 2][a_row] = av.z;
        As[0][a_col4 + 3][a_row] = av.w;
        *reinterpret_cast<float4*>(&Bs[0][b_row][b_col4]) = bv;
    }
    __syncthreads();

    const int nsteps = K / BK;
    for (int k0 = 0; k0 < nsteps; k0++) {
        const int buf = k0 & 1;
        float4 av, bv;
        const bool has_next = (k0 + 1) < nsteps;
        if (has_next) {
            const float* ap = a_ptr + (size_t)(k0 + 1) * BK;
            av = a_ok ? *reinterpret_cast<const float4*>(ap)
                      : make_float4(0.f, 0.f, 0.f, 0.f);
            bv = *reinterpret_cast<const float4*>(b_ptr + (size_t)(k0 + 1) * BK * N);
        }

        #pragma unroll
        for (int k = 0; k < BK; k++) {
            float4 ra0 = *reinterpret_cast<const float4*>(&As[buf][k][ty * 4]);
            float4 ra1 = *reinterpret_cast<const float4*>(&As[buf][k][ty * 4 + 64]);
            float4 rb0 = *reinterpret_cast<const float4*>(&Bs[buf][k][tx * 4]);
            float4 rb1 = *reinterpret_cast<const float4*>(&Bs[buf][k][tx * 4 + 64]);
            const float ra[8] = {ra0.x, ra0.y, ra0.z, ra0.w, ra1.x, ra1.y, ra1.z, ra1.w};
            const float rb[8] = {rb0.x, rb0.y, rb0.z, rb0.w, rb1.x, rb1.y, rb1.z, rb1.w};
            #pragma unroll
            for (int i = 0; i < 8; i++)
                #pragma unroll
                for (int j = 0; j < 8; j++) acc[i][j] += ra[i] * rb[j];
        }

        if (has_next) {
            const int nb = buf ^ 1;
            As[nb][a_col4 + 0][a_row] = av.x;
            As[nb][a_col4 + 1][a_row] = av.y;
            As[nb][a_col4 + 2][a_row] = av.z;
            As[nb][a_col4 + 3][a_row] = av.w;
            *reinterpret_cast<float4*>(&Bs[nb][b_row][b_col4]) = bv;
            __syncthreads();
        }
    }

    #pragma unroll
    for (int i = 0; i < 8; i++) {
        const int lr = (i < 4) ? (ty * 4 + i) : (64 + ty * 4 + i - 4);
        const int gr = block_row + lr;
        if (gr < M) {
            const float d = g_dinv[gr];
            float4 v0 = make_float4(acc[i][0] * d, acc[i][1] * d, acc[i][2] * d, acc[i][3] * d);
            float4 v1 = make_float4(acc[i][4] * d, acc[i][5] * d, acc[i][6] * d, acc[i][7] * d);
            *reinterpret_cast<float4*>(C + (size_t)gr * N + block_col + tx * 4) = v0;
            *reinterpret_cast<float4*>(C + (size_t)gr * N + block_col + 64 + tx * 4) = v1;
        }
    }
}

// ---------------- pull aggregation over pre-scaled rows ---------------------
// out[v] = relu( dinv[v] * ( sum_{src in N(v)} h'[src] + h'[v] ) + b )
template <int F>
__global__ void aggregate_warp_kernel(const float* __restrict__ h,
                                      const float* __restrict__ bias,
                                      float* __restrict__ out) {
    constexpr int NV = F / 128;              // float4 chunks per lane
    const int w    = threadIdx.x >> 5;
    const int lane = threadIdx.x & 31;
    const int v = blockIdx.x * 8 + w;
    if (v >= NNODES) return;

    const float dv = g_dinv[v];

    float4 acc[NV];
    {
        const float4* hv = reinterpret_cast<const float4*>(h + (size_t)v * F);
        #pragma unroll
        for (int i = 0; i < NV; i++) acc[i] = __ldg(&hv[lane + 32 * i]);
    }

    const int beg = g_rowptr[v];
    const int end = g_rowptr[v + 1];
    int j = beg;
    for (; j + 4 <= end; j += 4) {
        const int s0 = __ldg(&g_srcs[j + 0]);
        const int s1 = __ldg(&g_srcs[j + 1]);
        const int s2 = __ldg(&g_srcs[j + 2]);
        const int s3 = __ldg(&g_srcs[j + 3]);
        const float4* p0 = reinterpret_cast<const float4*>(h + (size_t)s0 * F);
        const float4* p1 = reinterpret_cast<const float4*>(h + (size_t)s1 * F);
        const float4* p2 = reinterpret_cast<const float4*>(h + (size_t)s2 * F);
        const float4* p3 = reinterpret_cast<const float4*>(h + (size_t)s3 * F);
        #pragma unroll
        for (int i = 0; i < NV; i++) {
            const int c = lane + 32 * i;
            float4 t0 = __ldg(&p0[c]);
            float4 t1 = __ldg(&p1[c]);
            float4 t2 = __ldg(&p2[c]);
            float4 t3 = __ldg(&p3[c]);
            acc[i].x += (t0.x + t1.x) + (t2.x + t3.x);
            acc[i].y += (t0.y + t1.y) + (t2.y + t3.y);
            acc[i].z += (t0.z + t1.z) + (t2.z + t3.z);
            acc[i].w += (t0.w + t1.w) + (t2.w + t3.w);
        }
    }
    for (; j < end; j++) {
        const int s = __ldg(&g_srcs[j]);
        const float4* p = reinterpret_cast<const float4*>(h + (size_t)s * F);
        #pragma unroll
        for (int i = 0; i < NV; i++) {
            float4 t = __ldg(&p[lane + 32 * i]);
            acc[i].x += t.x; acc[i].y += t.y; acc[i].z += t.z; acc[i].w += t.w;
        }
    }

    const float4* bptr = reinterpret_cast<const float4*>(bias);
    float4* optr = reinterpret_cast<float4*>(out + (size_t)v * F);
    #pragma unroll
    for (int i = 0; i < NV; i++) {
        float4 b = bptr[lane + 32 * i];
        float4 o;
        o.x = fmaxf(acc[i].x * dv + b.x, 0.f);
        o.y = fmaxf(acc[i].y * dv + b.y, 0.f);
        o.z = fmaxf(acc[i].z * dv + b.z, 0.f);
        o.w = fmaxf(acc[i].w * dv + b.w, 0.f);
        optr[lane + 32 * i] = o;
    }
}

// ---------------- launch ----------------------------------------------------
// Launch order puts aggregate_warp_kernel<512> at my-launch-index 3 — the slot
// the fixed ncu "-s 5 -c 1" capture lands on (verified: R4 idx3=scan, R6
// idx3=sgemm). This round profiles the suspected-hot aggregation kernel.
extern "C" void kernel_launch(void* const* d_in, const int* in_sizes, int n_in,
                              void* d_out, int out_size) {
    const float* x  = (const float*)d_in[0];
    const void*  ei = d_in[1];
    const float* W1 = (const float*)d_in[2];
    const float* b1 = (const float*)d_in[3];
    const float* W2 = (const float*)d_in[4];
    const float* b2 = (const float*)d_in[5];
    float* out = (float*)d_out;

    preprocess_kernel<<<1, 1024>>>(ei);                                       // 0

    {                                                                         // 1
        dim3 grid(F_HID / 128, (NNODES + 127) / 128);
        sgemm128_scaled_kernel<<<grid, 256>>>(x, W1, g_h1, NNODES, F_HID, F_IN);
    }

    warm_kernel<<<160, 256>>>();                                              // 2

    aggregate_warp_kernel<F_HID><<<(NNODES + 7) / 8, 256>>>(g_h1, b1, g_a1);  // 3 (capture)

    {                                                                         // 4
        dim3 grid(F_OUT / 128, (NNODES + 127) / 128);
        sgemm128_scaled_kernel<<<grid, 256>>>(g_a1, W2, g_h2, NNODES, F_OUT, F_HID);
    }
    aggregate_warp_kernel<F_OUT><<<(NNODES + 7) / 8, 256>>>(g_h2, b2, out);   // 5
}

// round 8
// speedup vs baseline: 1.0133x; 1.0053x over previous
#include <cuda_runtime.h>
#include <cuda_bf16.h>
#include <cstdint>

#define NNODES 20000
#define NEDGES 160000
#define F_IN   512
#define F_HID  512
#define F_OUT  256

// ---------------- scratch (device globals; no allocation APIs allowed) -----
__device__ int   g_is64;
__device__ int   g_deg[NNODES];
__device__ int   g_rowptr[NNODES + 1];
__device__ int   g_cursor[NNODES];
__device__ int   g_srcs[NEDGES];
__device__ __align__(16) float g_dinv[NNODES];
__device__ __align__(16) float g_h1[(size_t)NNODES * F_HID];   // x@W1, later *dinv
__device__ __align__(16) float g_a1[(size_t)NNODES * F_HID];
__device__ __align__(16) float g_h2[(size_t)NNODES * F_OUT];   // (a1@W2)*dinv

// ---------------- preprocessing (multi-block, known-fast) -------------------
__global__ void deg_count_kernel(const void* ei) {
    const int e = blockIdx.x * blockDim.x + threadIdx.x;
    if (e < NEDGES) {
        int dst;
        if (g_is64) dst = (int)((const long long*)ei)[NEDGES + e];
        else        dst = ((const int*)ei)[NEDGES + e];
        atomicAdd(&g_deg[dst], 1);
    }
}

// single block: exclusive scan -> rowptr/cursor, and dinv
__global__ void scan_dinv_kernel() {
    __shared__ int part[1024];
    const int t = threadIdx.x;
    const int CH = (NNODES + 1023) / 1024;     // 20
    const int base = t * CH;
    int s = 0;
    for (int i = 0; i < CH; i++) {
        int idx = base + i;
        if (idx < NNODES) s += g_deg[idx];
    }
    part[t] = s;
    __syncthreads();
    for (int off = 1; off < 1024; off <<= 1) {
        int v = (t >= off) ? part[t - off] : 0;
        __syncthreads();
        part[t] += v;
        __syncthreads();
    }
    int run = (t > 0) ? part[t - 1] : 0;
    for (int i = 0; i < CH; i++) {
        int idx = base + i;
        if (idx < NNODES) {
            g_rowptr[idx] = run;
            g_cursor[idx] = run;
            g_dinv[idx] = rsqrtf(1.0f + (float)g_deg[idx]);
            run += g_deg[idx];
        }
    }
    if (t == 1023) g_rowptr[NNODES] = part[1023];
}

__global__ void fill_kernel(const void* ei) {
    const int e = blockIdx.x * blockDim.x + threadIdx.x;
    if (e < NEDGES) {
        int src, dst;
        if (g_is64) {
            const long long* p = (const long long*)ei;
            src = (int)p[e]; dst = (int)p[NEDGES + e];
        } else {
            const int* p = (const int*)ei;
            src = p[e]; dst = p[NEDGES + e];
        }
        int pos = atomicAdd(&g_cursor[dst], 1);
        g_srcs[pos] = src;
    }
}

// scale rows of h by dinv[row] (for layer 1, where GEMM ran before dinv)
template <int F>
__global__ void scale_rows_kernel(float* __restrict__ h) {
    const int total4 = NNODES * F / 4;
    for (int idx = blockIdx.x * blockDim.x + threadIdx.x; idx < total4;
         idx += gridDim.x * blockDim.x) {
        const int node = idx / (F / 4);
        const float d = g_dinv[node];
        float4 v = reinterpret_cast<float4*>(h)[idx];
        v.x *= d; v.y *= d; v.z *= d; v.w *= d;
        reinterpret_cast<float4*>(h)[idx] = v;
    }
}

// ---------------- SIMT fp32 GEMM, 128x128x8, 8x8/thread, double-buffered ---
// SCALE_OUT: multiply output row r by g_dinv[r] (requires dinv valid).
// DO_PREP: embed dtype-detect + g_deg zeroing in the preamble (for layer 1,
// which runs before any preprocessing).
template <bool SCALE_OUT, bool DO_PREP>
__global__ __launch_bounds__(256, 2)
void sgemm128_kernel(const float* __restrict__ A, const float* __restrict__ B,
                     float* __restrict__ C, int M, int N, int K,
                     const void* ei) {
    if (DO_PREP) {
        const int gtid = (blockIdx.y * gridDim.x + blockIdx.x) * blockDim.x + threadIdx.x;
        if (gtid == 0) {
            const int* p = (const int*)ei;
            int is64 = 1;
            for (int i = 1; i < 64; i += 2)
                if (p[i] != 0) { is64 = 0; break; }
            g_is64 = is64;
        }
        if (gtid < NNODES) g_deg[gtid] = 0;
    }

    constexpr int BM = 128, BN = 128, BK = 8;
    __shared__ float As[2][BK][BM];
    __shared__ float Bs[2][BK][BN];

    const int tid = threadIdx.x;
    const int block_row = blockIdx.y * BM;
    const int block_col = blockIdx.x * BN;

    const int a_row  = tid >> 1;
    const int a_col4 = (tid & 1) * 4;
    const int b_row  = tid >> 5;
    const int b_col4 = (tid & 31) * 4;

    const int ty = tid >> 4;
    const int tx = tid & 15;

    const int a_g_row = block_row + a_row;
    const bool a_ok = a_g_row < M;
    const float* a_ptr = A + (size_t)(a_ok ? a_g_row : 0) * K + a_col4;
    const float* b_ptr = B + (size_t)b_row * N + block_col + b_col4;

    float acc[8][8];
    #pragma unroll
    for (int i = 0; i < 8; i++)
        #pragma unroll
        for (int j = 0; j < 8; j++) acc[i][j] = 0.f;

    {
        float4 av = a_ok ? *reinterpret_cast<const float4*>(a_ptr)
                         : make_float4(0.f, 0.f, 0.f, 0.f);
        float4 bv = *reinterpret_cast<const float4*>(b_ptr);
        As[0][a_col4 + 0][a_row] = av.x;
        As[0][a_col4 + 1][a_row] = av.y;
        As[0][a_col4 + 2][a_row] = av.z;
        As[0][a_col4 + 3][a_row] = av.w;
        *reinterpret_cast<float4*>(&Bs[0][b_row][b_col4]) = bv;
    }
    __syncthreads();

    const int nsteps = K / BK;
    for (int k0 = 0; k0 < nsteps; k0++) {
        const int buf = k0 & 1;
        float4 av, bv;
        const bool has_next = (k0 + 1) < nsteps;
        if (has_next) {
            const float* ap = a_ptr + (size_t)(k0 + 1) * BK;
            av = a_ok ? *reinterpret_cast<const float4*>(ap)
                      : make_float4(0.f, 0.f, 0.f, 0.f);
            bv = *reinterpret_cast<const float4*>(b_ptr + (size_t)(k0 + 1) * BK * N);
        }

        #pragma unroll
        for (int k = 0; k < BK; k++) {
            float4 ra0 = *reinterpret_cast<const float4*>(&As[buf][k][ty * 4]);
            float4 ra1 = *reinterpret_cast<const float4*>(&As[buf][k][ty * 4 + 64]);
            float4 rb0 = *reinterpret_cast<const float4*>(&Bs[buf][k][tx * 4]);
            float4 rb1 = *reinterpret_cast<const float4*>(&Bs[buf][k][tx * 4 + 64]);
            const float ra[8] = {ra0.x, ra0.y, ra0.z, ra0.w, ra1.x, ra1.y, ra1.z, ra1.w};
            const float rb[8] = {rb0.x, rb0.y, rb0.z, rb0.w, rb1.x, rb1.y, rb1.z, rb1.w};
            #pragma unroll
            for (int i = 0; i < 8; i++)
                #pragma unroll
                for (int j = 0; j < 8; j++) acc[i][j] += ra[i] * rb[j];
        }

        if (has_next) {
            const int nb = buf ^ 1;
            As[nb][a_col4 + 0][a_row] = av.x;
            As[nb][a_col4 + 1][a_row] = av.y;
            As[nb][a_col4 + 2][a_row] = av.z;
            As[nb][a_col4 + 3][a_row] = av.w;
            *reinterpret_cast<float4*>(&Bs[nb][b_row][b_col4]) = bv;
            __syncthreads();
        }
    }

    #pragma unroll
    for (int i = 0; i < 8; i++) {
        const int lr = (i < 4) ? (ty * 4 + i) : (64 + ty * 4 + i - 4);
        const int gr = block_row + lr;
        if (gr < M) {
            const float d = SCALE_OUT ? g_dinv[gr] : 1.0f;
            float4 v0 = make_float4(acc[i][0] * d, acc[i][1] * d, acc[i][2] * d, acc[i][3] * d);
            float4 v1 = make_float4(acc[i][4] * d, acc[i][5] * d, acc[i][6] * d, acc[i][7] * d);
            *reinterpret_cast<float4*>(C + (size_t)gr * N + block_col + tx * 4) = v0;
            *reinterpret_cast<float4*>(C + (size_t)gr * N + block_col + 64 + tx * 4) = v1;
        }
    }
}

// ---------------- pull aggregation over pre-scaled rows (UNCHANGED R7) -----
// out[v] = relu( dinv[v] * ( sum_{src in N(v)} h'[src] + h'[v] ) + b )
template <int F>
__global__ void aggregate_warp_kernel(const float* __restrict__ h,
                                      const float* __restrict__ bias,
                                      float* __restrict__ out) {
    constexpr int NV = F / 128;
    const int w    = threadIdx.x >> 5;
    const int lane = threadIdx.x & 31;
    const int v = blockIdx.x * 8 + w;
    if (v >= NNODES) return;

    const float dv = g_dinv[v];

    float4 acc[NV];
    {
        const float4* hv = reinterpret_cast<const float4*>(h + (size_t)v * F);
        #pragma unroll
        for (int i = 0; i < NV; i++) acc[i] = __ldg(&hv[lane + 32 * i]);
    }

    const int beg = g_rowptr[v];
    const int end = g_rowptr[v + 1];
    int j = beg;
    for (; j + 4 <= end; j += 4) {
        const int s0 = __ldg(&g_srcs[j + 0]);
        const int s1 = __ldg(&g_srcs[j + 1]);
        const int s2 = __ldg(&g_srcs[j + 2]);
        const int s3 = __ldg(&g_srcs[j + 3]);
        const float4* p0 = reinterpret_cast<const float4*>(h + (size_t)s0 * F);
        const float4* p1 = reinterpret_cast<const float4*>(h + (size_t)s1 * F);
        const float4* p2 = reinterpret_cast<const float4*>(h + (size_t)s2 * F);
        const float4* p3 = reinterpret_cast<const float4*>(h + (size_t)s3 * F);
        #pragma unroll
        for (int i = 0; i < NV; i++) {
            const int c = lane + 32 * i;
            float4 t0 = __ldg(&p0[c]);
            float4 t1 = __ldg(&p1[c]);
            float4 t2 = __ldg(&p2[c]);
            float4 t3 = __ldg(&p3[c]);
            acc[i].x += (t0.x + t1.x) + (t2.x + t3.x);
            acc[i].y += (t0.y + t1.y) + (t2.y + t3.y);
            acc[i].z += (t0.z + t1.z) + (t2.z + t3.z);
            acc[i].w += (t0.w + t1.w) + (t2.w + t3.w);
        }
    }
    for (; j < end; j++) {
        const int s = __ldg(&g_srcs[j]);
        const float4* p = reinterpret_cast<const float4*>(h + (size_t)s * F);
        #pragma unroll
        for (int i = 0; i < NV; i++) {
            float4 t = __ldg(&p[lane + 32 * i]);
            acc[i].x += t.x; acc[i].y += t.y; acc[i].z += t.z; acc[i].w += t.w;
        }
    }

    const float4* bptr = reinterpret_cast<const float4*>(bias);
    float4* optr = reinterpret_cast<float4*>(out + (size_t)v * F);
    #pragma unroll
    for (int i = 0; i < NV; i++) {
        float4 b = bptr[lane + 32 * i];
        float4 o;
        o.x = fmaxf(acc[i].x * dv + b.x, 0.f);
        o.y = fmaxf(acc[i].y * dv + b.y, 0.f);
        o.z = fmaxf(acc[i].z * dv + b.z, 0.f);
        o.w = fmaxf(acc[i].w * dv + b.w, 0.f);
        optr[lane + 32 * i] = o;
    }
}

// ---------------- launch ----------------------------------------------------
// Multi-block preprocessing restored (known ~60-90us from R4/R5 arithmetic).
// Aggregate kernel byte-identical to R7 — controlled experiment:
//   total ~= 844(gemms) + ~110(prep+scale) + agg_total.
extern "C" void kernel_launch(void* const* d_in, const int* in_sizes, int n_in,
                              void* d_out, int out_size) {
    const float* x  = (const float*)d_in[0];
    const void*  ei = d_in[1];
    const float* W1 = (const float*)d_in[2];
    const float* b1 = (const float*)d_in[3];
    const float* W2 = (const float*)d_in[4];
    const float* b2 = (const float*)d_in[5];
    float* out = (float*)d_out;

    {   // 0: h1 = x@W1 (unscaled), embeds dtype detect + deg zeroing
        dim3 grid(F_HID / 128, (NNODES + 127) / 128);
        sgemm128_kernel<false, true><<<grid, 256>>>(x, W1, g_h1, NNODES, F_HID, F_IN, ei);
    }
    deg_count_kernel<<<(NEDGES + 255) / 256, 256>>>(ei);            // 1
    scan_dinv_kernel<<<1, 1024>>>();                                // 2
    fill_kernel<<<(NEDGES + 255) / 256, 256>>>(ei);                 // 3 (capture)
    scale_rows_kernel<F_HID><<<2048, 256>>>(g_h1);                  // 4: h1 *= dinv
    aggregate_warp_kernel<F_HID><<<(NNODES + 7) / 8, 256>>>(g_h1, b1, g_a1);  // 5

    {   // 6: h2 = (a1@W2)*dinv (fused scale)
        dim3 grid(F_OUT / 128, (NNODES + 127) / 128);
        sgemm128_kernel<true, false><<<grid, 256>>>(g_a1, W2, g_h2, NNODES, F_OUT, F_HID, ei);
    }
    aggregate_warp_kernel<F_OUT><<<(NNODES + 7) / 8, 256>>>(g_h2, b2, out);   // 7
}